// round 16
// baseline (speedup 1.0000x reference)
#include <cuda_runtime.h>
#include <cuda_fp16.h>
#include <math.h>

#define NN 100000
#define EE 3200000
#define E2B ((EE / 2 + 255) / 256)   // fill blocks (2 edges per thread)
#define GB ((NN + 255) / 256)        // gemm blocks
#define BK 128                       // bucket capacity per node (P(deg>128) ~ 1e-40)

typedef unsigned long long ull;

// ---------------- scratch (__device__ globals; no allocs allowed) ----------------
// pad row (index NN) of g_hh is never written; module-load zero-init keeps it 0.
__device__ __half2 g_hh[(size_t)(NN + 1) * 32]; // 12.8 MB; row NN = zeros (pad row)
__device__ __half2 g_hf[(size_t)NN * 32];       // 12.8 MB  (agg output, fp16)
__device__ int     g_bucket[(size_t)NN * BK];   // 51.2 MB (src indices, 128-slot buckets)
__device__ int     g_cursor[NN];                // zero at load; re-zeroed by k_scale2
__device__ int     g_deg[NN];
__device__ float   g_dinv[NN];

// ---------------- packed f32x2 helpers ----------------
__device__ __forceinline__ void ffma2(ull& d, ull a, ull b) {
    asm("fma.rn.f32x2 %0, %1, %2, %0;" : "+l"(d) : "l"(a), "l"(b));
}
__device__ __forceinline__ void fadd2(ull& d, ull a) {
    asm("add.rn.f32x2 %0, %0, %1;" : "+l"(d) : "l"(a));
}
__device__ __forceinline__ ull bcast2(float x) {
    unsigned u = __float_as_uint(x);
    return ((ull)u << 32) | (ull)u;
}

// per-thread int64-vs-int32 detect: odd 32-bit words of first 4 int64 values are 0.
__device__ __forceinline__ bool detect64(const void* edges) {
    uint4 h0 = ((const uint4*)edges)[0];
    uint4 h1 = ((const uint4*)edges)[1];
    return ((h0.y | h0.w | h1.y | h1.w) == 0u);
}

// ---------------- single-pass bucket fill: rank via atomic, direct placement ----------
__global__ void k_fillb(const void* edges) {
    int e2 = blockIdx.x * blockDim.x + threadIdx.x;
    if (e2 >= EE / 2) return;
    int s0, s1, d0, d1;
    if (detect64(edges)) {
        longlong2 qs = ((const longlong2*)edges)[e2];
        longlong2 qd = ((const longlong2*)edges)[EE / 2 + e2];
        s0 = (int)qs.x; s1 = (int)qs.y;
        d0 = (int)qd.x; d1 = (int)qd.y;
    } else {
        int2 qs = ((const int2*)edges)[e2];
        int2 qd = ((const int2*)edges)[EE / 2 + e2];
        s0 = qs.x; s1 = qs.y;
        d0 = qd.x; d1 = qd.y;
    }
    int r0 = atomicAdd(&g_cursor[d0], 1);
    int r1 = atomicAdd(&g_cursor[d1], 1);
    if (r0 < BK) g_bucket[(size_t)d0 * BK + r0] = s0;
    if (r1 < BK) g_bucket[(size_t)d1 * BK + r1] = s1;
}

// ---------------- GEMM1 (no prescale): H[r] = X[r] @ W, fp32 in, fp16 out ----------------
__global__ __launch_bounds__(256)
void k_gemm128(const float* __restrict__ X, const float* __restrict__ W,
               __half2* __restrict__ C) {
    __shared__ float Ws[128 * 64];
    for (int i = threadIdx.x; i < 128 * 16; i += 256) {
        ((float4*)Ws)[i] = ((const float4*)W)[i];
    }
    __syncthreads();
    int r = blockIdx.x * 256 + threadIdx.x;
    if (r >= NN) return;

    ull acc[32];
    #pragma unroll
    for (int j = 0; j < 32; j++) acc[j] = 0ull;

    const float4* xr = (const float4*)(X + (size_t)r * 128);
    #pragma unroll 2
    for (int k4 = 0; k4 < 32; k4++) {
        float4 xv = xr[k4];
        float xk[4] = {xv.x, xv.y, xv.z, xv.w};
        #pragma unroll
        for (int kk = 0; kk < 4; kk++) {
            const ull* wr = (const ull*)&Ws[(k4 * 4 + kk) * 64];
            ull xs2 = bcast2(xk[kk]);
            #pragma unroll
            for (int j = 0; j < 32; j++) ffma2(acc[j], xs2, wr[j]);
        }
    }
    __half2 hv[32];
    #pragma unroll
    for (int j = 0; j < 32; j++) {
        float2 f = *(float2*)&acc[j];
        hv[j] = __floats2half2_rn(f.x, f.y);
    }
    uint4* cr = (uint4*)(C + (size_t)r * 32);
    const uint4* hv4 = (const uint4*)hv;
    #pragma unroll
    for (int j = 0; j < 8; j++) cr[j] = hv4[j];
}

// ---------------- scale2: dinv/deg from cursor, scale hh, re-arm cursor ----------------
__global__ __launch_bounds__(256)
void k_scale2(uint4* __restrict__ H) {
    int i = blockIdx.x * 256 + threadIdx.x;   // uint4 index; 8 per row
    if (i >= NN * 8) return;
    int r = i >> 3;
    int c = g_cursor[r];
    if (c > BK) c = BK;
    float dv = rsqrtf((float)(c + 1));
    uint4 q = H[i];
    __half2* h = (__half2*)&q;
    #pragma unroll
    for (int j = 0; j < 4; j++) {
        float2 f = __half22float2(h[j]);
        h[j] = __floats2half2_rn(f.x * dv, f.y * dv);
    }
    H[i] = q;
    if ((i & 7) == 0) {
        g_deg[r]    = c;
        g_dinv[r]   = dv;
        g_cursor[r] = 0;   // re-arm for next replay
    }
}

// ---------------- GEMM2: fp16 in (64 ch), fp16 out, prescaled by dinv ----------------
__global__ __launch_bounds__(256)
void k_gemm64h(const __half2* __restrict__ X, const float* __restrict__ W,
               __half2* __restrict__ C) {
    __shared__ float Ws[64 * 64];
    for (int i = threadIdx.x; i < 64 * 16; i += 256) {
        ((float4*)Ws)[i] = ((const float4*)W)[i];
    }
    __syncthreads();
    int r = blockIdx.x * 256 + threadIdx.x;
    if (r >= NN) return;

    ull acc[32];
    #pragma unroll
    for (int j = 0; j < 32; j++) acc[j] = 0ull;

    const uint4* xr = (const uint4*)(X + (size_t)r * 32);
    #pragma unroll
    for (int q = 0; q < 8; q++) {
        uint4 xq = xr[q];
        float2 f0 = __half22float2(*(__half2*)&xq.x);
        float2 f1 = __half22float2(*(__half2*)&xq.y);
        float2 f2 = __half22float2(*(__half2*)&xq.z);
        float2 f3 = __half22float2(*(__half2*)&xq.w);
        float xk[8] = {f0.x, f0.y, f1.x, f1.y, f2.x, f2.y, f3.x, f3.y};
        #pragma unroll
        for (int kk = 0; kk < 8; kk++) {
            const ull* wr = (const ull*)&Ws[(q * 8 + kk) * 64];
            ull xs2 = bcast2(xk[kk]);
            #pragma unroll
            for (int j = 0; j < 32; j++) ffma2(acc[j], xs2, wr[j]);
        }
    }
    float dv = g_dinv[r];
    __half2 hv[32];
    #pragma unroll
    for (int j = 0; j < 32; j++) {
        float2 f = *(float2*)&acc[j];
        hv[j] = __floats2half2_rn(f.x * dv, f.y * dv);
    }
    uint4* cr = (uint4*)(C + (size_t)r * 32);
    const uint4* hv4 = (const uint4*)hv;
    #pragma unroll
    for (int j = 0; j < 8; j++) cr[j] = hv4[j];
}

// ---------------- aggregation: bucket CSR, fp16 pair-add + packed f32x2 accumulate ----
// pair: one HADD2 per half2, convert pair-sum once, f32x2 accumulate.
__device__ __forceinline__ void addp(ull* a, uint4 qa, uint4 qb) {
    __half2* ha = (__half2*)&qa;
    __half2* hb = (__half2*)&qb;
    #pragma unroll
    for (int j = 0; j < 4; j++) {
        __half2 s = __hadd2(ha[j], hb[j]);
        float2 f = __half22float2(s);
        fadd2(a[j], *(ull*)&f);
    }
}
// single edge: convert directly, f32x2 accumulate (no fp16 add).
__device__ __forceinline__ void adds(ull* a, uint4 q) {
    __half2* h = (__half2*)&q;
    #pragma unroll
    for (int j = 0; j < 4; j++) {
        float2 f = __half22float2(h[j]);
        fadd2(a[j], *(ull*)&f);
    }
}

__global__ __launch_bounds__(256)
void k_agg(const uint4* __restrict__ H4, const float* __restrict__ b,
           __half2* __restrict__ out) {
    __shared__ int s_idx[8][2][32];   // double-buffered per warp
    int w = threadIdx.x >> 5;
    int lane = threadIdx.x & 31;
    int g = lane >> 3;     // edge slot within group-of-4
    int c = lane & 7;      // 16B chunk within 128B row
    int v = blockIdx.x * 8 + w;
    if (v >= NN) return;
    int beg = v * BK;
    int end = beg + g_deg[v];
    float dv = g_dinv[v];

    ull aA[4] = {0ull, 0ull, 0ull, 0ull};
    ull aB[4] = {0ull, 0ull, 0ull, 0ull};

    // prime: load first chunk's indices into a register
    int s_cur = (beg + lane < end) ? g_bucket[beg + lane] : NN;

    int buf = 0;
    for (int e = beg; e < end; e += 32, buf ^= 1) {
        int cnt = min(32, end - e);
        int* sw = s_idx[w][buf];
        sw[lane] = s_cur;
        __syncwarp();
        // issue next chunk's index load NOW — it flies while we gather this chunk
        int nidx = e + 32 + lane;
        if (e + 32 < end) s_cur = (nidx < end) ? g_bucket[nidx] : NN;

        if (cnt == 32) {
            int i0 = sw[0 * 4 + g], i1 = sw[1 * 4 + g], i2 = sw[2 * 4 + g], i3 = sw[3 * 4 + g];
            int i4 = sw[4 * 4 + g], i5 = sw[5 * 4 + g], i6 = sw[6 * 4 + g], i7 = sw[7 * 4 + g];
            uint4 q0 = H4[i0 * 8 + c];
            uint4 q1 = H4[i1 * 8 + c];
            uint4 q2 = H4[i2 * 8 + c];
            uint4 q3 = H4[i3 * 8 + c];
            uint4 q4 = H4[i4 * 8 + c];
            uint4 q5 = H4[i5 * 8 + c];
            uint4 q6 = H4[i6 * 8 + c];
            uint4 q7 = H4[i7 * 8 + c];
            addp(aA, q0, q1);
            addp(aB, q2, q3);
            addp(aA, q4, q5);
            addp(aB, q6, q7);
        } else {
            int iters = (cnt + 3) >> 2;
            int k = 0;
            for (; k + 2 <= iters; k += 2) {
                int i0 = sw[k * 4 + g];
                int i1 = sw[k * 4 + 4 + g];
                uint4 q0 = H4[i0 * 8 + c];
                uint4 q1 = H4[i1 * 8 + c];
                addp(aA, q0, q1);
            }
            if (k < iters) {
                int i0 = sw[k * 4 + g];
                uint4 q0 = H4[i0 * 8 + c];
                adds(aB, q0);
            }
        }
        __syncwarp();
    }

    // self-loop term: add row v exactly once (group 0 only)
    if (g == 0) {
        uint4 qv = H4[v * 8 + c];
        adds(aA, qv);
    }

    // unpack, merge A/B, cross-group butterfly
    float acc[8];
    #pragma unroll
    for (int j = 0; j < 4; j++) {
        float2 fa = *(float2*)&aA[j];
        float2 fb = *(float2*)&aB[j];
        float x = fa.x + fb.x;
        float y = fa.y + fb.y;
        x += __shfl_xor_sync(0xffffffffu, x, 8);
        x += __shfl_xor_sync(0xffffffffu, x, 16);
        y += __shfl_xor_sync(0xffffffffu, y, 8);
        y += __shfl_xor_sync(0xffffffffu, y, 16);
        acc[2 * j]     = x;
        acc[2 * j + 1] = y;
    }

    int ch = 8 * c + 2 * g;
    float2 bb = *(const float2*)(b + ch);
    float ox = acc[2 * g]     * dv + bb.x;
    float oy = acc[2 * g + 1] * dv + bb.y;
    out[(size_t)v * 32 + (ch >> 1)] = __floats2half2_rn(ox, oy);
}

// ---------------- fused MLP head (fp16 input), packed f32x2 FMA ----------------
__global__ __launch_bounds__(128)
void k_mlp(const __half2* __restrict__ h,
           const float* __restrict__ lw1, const float* __restrict__ lb1,
           const float* __restrict__ lw2, const float* __restrict__ lb2,
           const float* __restrict__ lw3, const float* __restrict__ lb3,
           float* __restrict__ out) {
    __shared__ float s_w1[64 * 64];
    __shared__ float s_w2[64 * 32];
    __shared__ float s_w3[32];
    __shared__ float s_b1[64];
    __shared__ float s_b2[32];
    __shared__ float s_b3;
    int t = threadIdx.x;
    for (int i = t; i < 64 * 16; i += 128) ((float4*)s_w1)[i] = ((const float4*)lw1)[i];
    for (int i = t; i < 64 * 8;  i += 128) ((float4*)s_w2)[i] = ((const float4*)lw2)[i];
    if (t < 32) s_w3[t] = lw3[t];
    if (t < 64) s_b1[t] = lb1[t];
    if (t < 32) s_b2[t] = lb2[t];
    if (t == 0) s_b3 = lb3[0];
    __syncthreads();

    int v = blockIdx.x * 128 + t;
    if (v >= NN) return;

    float in[64];
    const uint4* hr = (const uint4*)(h + (size_t)v * 32);
    #pragma unroll
    for (int i = 0; i < 8; i++) {
        uint4 q = hr[i];
        float2 f0 = __half22float2(*(__half2*)&q.x);
        float2 f1 = __half22float2(*(__half2*)&q.y);
        float2 f2 = __half22float2(*(__half2*)&q.z);
        float2 f3 = __half22float2(*(__half2*)&q.w);
        in[8 * i + 0] = f0.x; in[8 * i + 1] = f0.y;
        in[8 * i + 2] = f1.x; in[8 * i + 3] = f1.y;
        in[8 * i + 4] = f2.x; in[8 * i + 5] = f2.y;
        in[8 * i + 6] = f3.x; in[8 * i + 7] = f3.y;
    }

    // layer1: 64 -> 64
    ull a1[32];
    #pragma unroll
    for (int j = 0; j < 32; j++) a1[j] = ((const ull*)s_b1)[j];
    #pragma unroll
    for (int k = 0; k < 64; k++) {
        ull xs2 = bcast2(in[k]);
        const ull* wr = (const ull*)&s_w1[k * 64];
        #pragma unroll
        for (int j = 0; j < 32; j++) ffma2(a1[j], xs2, wr[j]);
    }
    float t1[64];
    #pragma unroll
    for (int j = 0; j < 32; j++) {
        float2 f = *(float2*)&a1[j];
        t1[2 * j]     = fmaxf(f.x, 0.f);
        t1[2 * j + 1] = fmaxf(f.y, 0.f);
    }

    // layer2: 64 -> 32
    ull a2[16];
    #pragma unroll
    for (int j = 0; j < 16; j++) a2[j] = ((const ull*)s_b2)[j];
    #pragma unroll
    for (int k = 0; k < 64; k++) {
        ull xs2 = bcast2(t1[k]);
        const ull* wr = (const ull*)&s_w2[k * 32];
        #pragma unroll
        for (int j = 0; j < 16; j++) ffma2(a2[j], xs2, wr[j]);
    }
    float t2[32];
    #pragma unroll
    for (int j = 0; j < 16; j++) {
        float2 f = *(float2*)&a2[j];
        t2[2 * j]     = fmaxf(f.x, 0.f);
        t2[2 * j + 1] = fmaxf(f.y, 0.f);
    }

    // layer3: 32 -> 1
    float o = s_b3;
    #pragma unroll
    for (int k = 0; k < 32; k++) o += t2[k] * s_w3[k];
    out[v] = o;
}

// ---------------- launcher (two-stream fork/join, capture-safe) ----------------
extern "C" void kernel_launch(void* const* d_in, const int* in_sizes, int n_in,
                              void* d_out, int out_size) {
    const float* x   = (const float*)d_in[0];
    const void*  edg = d_in[1];
    const float* W1  = (const float*)d_in[2];
    const float* b1  = (const float*)d_in[3];
    const float* W2  = (const float*)d_in[4];
    const float* b2  = (const float*)d_in[5];
    const float* lw1 = (const float*)d_in[6];
    const float* lb1 = (const float*)d_in[7];
    const float* lw2 = (const float*)d_in[8];
    const float* lb2 = (const float*)d_in[9];
    const float* lw3 = (const float*)d_in[10];
    const float* lb3 = (const float*)d_in[11];
    float* out = (float*)d_out;

    __half2* hh; cudaGetSymbolAddress((void**)&hh, g_hh);
    __half2* hf; cudaGetSymbolAddress((void**)&hf, g_hf);

    // one-time host-side resources (created on the uncaptured correctness call)
    static cudaStream_t s1 = nullptr;
    static cudaEvent_t evStart = nullptr, evG = nullptr;
    if (s1 == nullptr) {
        cudaStreamCreateWithFlags(&s1, cudaStreamNonBlocking);
        cudaEventCreateWithFlags(&evStart, cudaEventDisableTiming);
        cudaEventCreateWithFlags(&evG,     cudaEventDisableTiming);
    }

    // fork: s1 runs gemm128 (input-only deps) under the bucket fill
    cudaEventRecord(evStart, 0);
    cudaStreamWaitEvent(s1, evStart, 0);
    k_gemm128<<<GB, 256, 0, s1>>>(x, W1, hh);
    cudaEventRecord(evG, s1);

    // main stream: single-pass bucket CSR build (cursor pre-zeroed)
    k_fillb<<<E2B, 256>>>(edg);

    // join gemm, then dinv/deg + scale + cursor re-arm
    cudaStreamWaitEvent(0, evG, 0);
    k_scale2<<<(NN * 8 + 255) / 256, 256>>>((uint4*)hh);

    // serial conv/MLP chain
    k_agg<<<(NN + 7) / 8, 256>>>((const uint4*)hh, b1, hf);
    k_gemm64h<<<GB, 256>>>(hf, W2, hh);
    k_agg<<<(NN + 7) / 8, 256>>>((const uint4*)hh, b2, hf);
    k_mlp<<<(NN + 127) / 128, 128>>>(hf, lw1, lb1, lw2, lb2, lw3, lb3, out);
}

// round 17
// speedup vs baseline: 1.0173x; 1.0173x over previous
#include <cuda_runtime.h>
#include <cuda_fp16.h>
#include <math.h>

#define NN 100000
#define EE 3200000
#define E2B ((EE / 2 + 255) / 256)   // fill blocks (2 edges per thread)
#define GB ((NN + 255) / 256)        // gemm blocks
#define BK 128                       // bucket capacity per node (P(deg>128) ~ 1e-40)

typedef unsigned long long ull;

// ---------------- scratch (__device__ globals; no allocs allowed) ----------------
// pad row (index NN) of g_hh is never written; module-load zero-init keeps it 0.
__device__ __half2 g_hh[(size_t)(NN + 1) * 32]; // 12.8 MB; row NN = zeros (pad row)
__device__ __half2 g_hf[(size_t)NN * 32];       // 12.8 MB  (agg output, fp16)
__device__ int     g_bucket[(size_t)NN * BK];   // 51.2 MB (src indices, 128-slot buckets)
__device__ int     g_cursor[NN];                // zero at load; re-zeroed by k_scale2
__device__ int     g_deg[NN];
__device__ float   g_dinv[NN];

// ---------------- packed f32x2 helpers ----------------
__device__ __forceinline__ void ffma2(ull& d, ull a, ull b) {
    asm("fma.rn.f32x2 %0, %1, %2, %0;" : "+l"(d) : "l"(a), "l"(b));
}
__device__ __forceinline__ void fadd2(ull& d, ull a) {
    asm("add.rn.f32x2 %0, %0, %1;" : "+l"(d) : "l"(a));
}
__device__ __forceinline__ ull bcast2(float x) {
    unsigned u = __float_as_uint(x);
    return ((ull)u << 32) | (ull)u;
}

// per-thread int64-vs-int32 detect: odd 32-bit words of first 4 int64 values are 0.
__device__ __forceinline__ bool detect64(const void* edges) {
    uint4 h0 = ((const uint4*)edges)[0];
    uint4 h1 = ((const uint4*)edges)[1];
    return ((h0.y | h0.w | h1.y | h1.w) == 0u);
}

// ---------------- single-pass bucket fill: rank via atomic, direct placement ----------
__global__ void k_fillb(const void* edges) {
    int e2 = blockIdx.x * blockDim.x + threadIdx.x;
    if (e2 >= EE / 2) return;
    int s0, s1, d0, d1;
    if (detect64(edges)) {
        longlong2 qs = ((const longlong2*)edges)[e2];
        longlong2 qd = ((const longlong2*)edges)[EE / 2 + e2];
        s0 = (int)qs.x; s1 = (int)qs.y;
        d0 = (int)qd.x; d1 = (int)qd.y;
    } else {
        int2 qs = ((const int2*)edges)[e2];
        int2 qd = ((const int2*)edges)[EE / 2 + e2];
        s0 = qs.x; s1 = qs.y;
        d0 = qd.x; d1 = qd.y;
    }
    int r0 = atomicAdd(&g_cursor[d0], 1);
    int r1 = atomicAdd(&g_cursor[d1], 1);
    if (r0 < BK) g_bucket[(size_t)d0 * BK + r0] = s0;
    if (r1 < BK) g_bucket[(size_t)d1 * BK + r1] = s1;
}

// ---------------- GEMM1 (no prescale): H[r] = X[r] @ W, fp32 in, fp16 out ----------------
__global__ __launch_bounds__(256)
void k_gemm128(const float* __restrict__ X, const float* __restrict__ W,
               __half2* __restrict__ C) {
    __shared__ float Ws[128 * 64];
    for (int i = threadIdx.x; i < 128 * 16; i += 256) {
        ((float4*)Ws)[i] = ((const float4*)W)[i];
    }
    __syncthreads();
    int r = blockIdx.x * 256 + threadIdx.x;
    if (r >= NN) return;

    ull acc[32];
    #pragma unroll
    for (int j = 0; j < 32; j++) acc[j] = 0ull;

    const float4* xr = (const float4*)(X + (size_t)r * 128);
    #pragma unroll 2
    for (int k4 = 0; k4 < 32; k4++) {
        float4 xv = xr[k4];
        float xk[4] = {xv.x, xv.y, xv.z, xv.w};
        #pragma unroll
        for (int kk = 0; kk < 4; kk++) {
            const ull* wr = (const ull*)&Ws[(k4 * 4 + kk) * 64];
            ull xs2 = bcast2(xk[kk]);
            #pragma unroll
            for (int j = 0; j < 32; j++) ffma2(acc[j], xs2, wr[j]);
        }
    }
    __half2 hv[32];
    #pragma unroll
    for (int j = 0; j < 32; j++) {
        float2 f = *(float2*)&acc[j];
        hv[j] = __floats2half2_rn(f.x, f.y);
    }
    uint4* cr = (uint4*)(C + (size_t)r * 32);
    const uint4* hv4 = (const uint4*)hv;
    #pragma unroll
    for (int j = 0; j < 8; j++) cr[j] = hv4[j];
}

// ---------------- scale2: dinv/deg from cursor, scale hh, re-arm cursor ----------------
__global__ __launch_bounds__(256)
void k_scale2(uint4* __restrict__ H) {
    int i = blockIdx.x * 256 + threadIdx.x;   // uint4 index; 8 per row
    if (i >= NN * 8) return;
    int r = i >> 3;
    int c = g_cursor[r];
    if (c > BK) c = BK;
    float dv = rsqrtf((float)(c + 1));
    uint4 q = H[i];
    __half2* h = (__half2*)&q;
    #pragma unroll
    for (int j = 0; j < 4; j++) {
        float2 f = __half22float2(h[j]);
        h[j] = __floats2half2_rn(f.x * dv, f.y * dv);
    }
    H[i] = q;
    if ((i & 7) == 0) {
        g_deg[r]    = c;
        g_dinv[r]   = dv;
        g_cursor[r] = 0;   // re-arm for next replay
    }
}

// ---------------- GEMM2: fp16 in (64 ch), fp16 out, prescaled by dinv ----------------
__global__ __launch_bounds__(256)
void k_gemm64h(const __half2* __restrict__ X, const float* __restrict__ W,
               __half2* __restrict__ C) {
    __shared__ float Ws[64 * 64];
    for (int i = threadIdx.x; i < 64 * 16; i += 256) {
        ((float4*)Ws)[i] = ((const float4*)W)[i];
    }
    __syncthreads();
    int r = blockIdx.x * 256 + threadIdx.x;
    if (r >= NN) return;

    ull acc[32];
    #pragma unroll
    for (int j = 0; j < 32; j++) acc[j] = 0ull;

    const uint4* xr = (const uint4*)(X + (size_t)r * 32);
    #pragma unroll
    for (int q = 0; q < 8; q++) {
        uint4 xq = xr[q];
        float2 f0 = __half22float2(*(__half2*)&xq.x);
        float2 f1 = __half22float2(*(__half2*)&xq.y);
        float2 f2 = __half22float2(*(__half2*)&xq.z);
        float2 f3 = __half22float2(*(__half2*)&xq.w);
        float xk[8] = {f0.x, f0.y, f1.x, f1.y, f2.x, f2.y, f3.x, f3.y};
        #pragma unroll
        for (int kk = 0; kk < 8; kk++) {
            const ull* wr = (const ull*)&Ws[(q * 8 + kk) * 64];
            ull xs2 = bcast2(xk[kk]);
            #pragma unroll
            for (int j = 0; j < 32; j++) ffma2(acc[j], xs2, wr[j]);
        }
    }
    float dv = g_dinv[r];
    __half2 hv[32];
    #pragma unroll
    for (int j = 0; j < 32; j++) {
        float2 f = *(float2*)&acc[j];
        hv[j] = __floats2half2_rn(f.x * dv, f.y * dv);
    }
    uint4* cr = (uint4*)(C + (size_t)r * 32);
    const uint4* hv4 = (const uint4*)hv;
    #pragma unroll
    for (int j = 0; j < 8; j++) cr[j] = hv4[j];
}

// ---------------- aggregation: bucket CSR, packed f32x2 accumulate (independent) ----
// per uint4: 8 F2F + 4 FADD2, each load feeds its own accumulator chain.
__device__ __forceinline__ void adds(ull* a, uint4 q) {
    __half2* h = (__half2*)&q;
    #pragma unroll
    for (int j = 0; j < 4; j++) {
        float2 f = __half22float2(h[j]);
        fadd2(a[j], *(ull*)&f);
    }
}

__global__ __launch_bounds__(256)
void k_agg(const uint4* __restrict__ H4, const float* __restrict__ b,
           __half2* __restrict__ out) {
    __shared__ int s_idx[8][2][32];   // double-buffered per warp
    int w = threadIdx.x >> 5;
    int lane = threadIdx.x & 31;
    int g = lane >> 3;     // edge slot within group-of-4
    int c = lane & 7;      // 16B chunk within 128B row
    int v = blockIdx.x * 8 + w;
    if (v >= NN) return;
    int beg = v * BK;
    int end = beg + g_deg[v];
    float dv = g_dinv[v];

    ull aA[4] = {0ull, 0ull, 0ull, 0ull};
    ull aB[4] = {0ull, 0ull, 0ull, 0ull};

    // prime: load first chunk's indices into a register
    int s_cur = (beg + lane < end) ? g_bucket[beg + lane] : NN;

    int buf = 0;
    for (int e = beg; e < end; e += 32, buf ^= 1) {
        int cnt = min(32, end - e);
        int* sw = s_idx[w][buf];
        sw[lane] = s_cur;
        __syncwarp();
        // issue next chunk's index load NOW — it flies while we gather this chunk
        int nidx = e + 32 + lane;
        if (e + 32 < end) s_cur = (nidx < end) ? g_bucket[nidx] : NN;

        if (cnt == 32) {
            int i0 = sw[0 * 4 + g], i1 = sw[1 * 4 + g], i2 = sw[2 * 4 + g], i3 = sw[3 * 4 + g];
            int i4 = sw[4 * 4 + g], i5 = sw[5 * 4 + g], i6 = sw[6 * 4 + g], i7 = sw[7 * 4 + g];
            uint4 q0 = H4[i0 * 8 + c];
            uint4 q1 = H4[i1 * 8 + c];
            uint4 q2 = H4[i2 * 8 + c];
            uint4 q3 = H4[i3 * 8 + c];
            uint4 q4 = H4[i4 * 8 + c];
            uint4 q5 = H4[i5 * 8 + c];
            uint4 q6 = H4[i6 * 8 + c];
            uint4 q7 = H4[i7 * 8 + c];
            adds(aA, q0); adds(aB, q1);
            adds(aA, q2); adds(aB, q3);
            adds(aA, q4); adds(aB, q5);
            adds(aA, q6); adds(aB, q7);
        } else {
            int iters = (cnt + 3) >> 2;
            int k = 0;
            for (; k + 2 <= iters; k += 2) {
                int i0 = sw[k * 4 + g];
                int i1 = sw[k * 4 + 4 + g];
                uint4 q0 = H4[i0 * 8 + c];
                uint4 q1 = H4[i1 * 8 + c];
                adds(aA, q0);
                adds(aB, q1);
            }
            if (k < iters) {
                int i0 = sw[k * 4 + g];
                uint4 q0 = H4[i0 * 8 + c];
                adds(aA, q0);
            }
        }
        __syncwarp();
    }

    // self-loop term: add row v exactly once (group 0 only)
    if (g == 0) {
        uint4 qv = H4[v * 8 + c];
        adds(aA, qv);
    }

    // unpack, merge A/B, cross-group butterfly
    float acc[8];
    #pragma unroll
    for (int j = 0; j < 4; j++) {
        float2 fa = *(float2*)&aA[j];
        float2 fb = *(float2*)&aB[j];
        float x = fa.x + fb.x;
        float y = fa.y + fb.y;
        x += __shfl_xor_sync(0xffffffffu, x, 8);
        x += __shfl_xor_sync(0xffffffffu, x, 16);
        y += __shfl_xor_sync(0xffffffffu, y, 8);
        y += __shfl_xor_sync(0xffffffffu, y, 16);
        acc[2 * j]     = x;
        acc[2 * j + 1] = y;
    }

    int ch = 8 * c + 2 * g;
    float2 bb = *(const float2*)(b + ch);
    float ox = acc[2 * g]     * dv + bb.x;
    float oy = acc[2 * g + 1] * dv + bb.y;
    out[(size_t)v * 32 + (ch >> 1)] = __floats2half2_rn(ox, oy);
}

// ---------------- fused MLP head (fp16 input), packed f32x2 FMA ----------------
__global__ __launch_bounds__(128)
void k_mlp(const __half2* __restrict__ h,
           const float* __restrict__ lw1, const float* __restrict__ lb1,
           const float* __restrict__ lw2, const float* __restrict__ lb2,
           const float* __restrict__ lw3, const float* __restrict__ lb3,
           float* __restrict__ out) {
    __shared__ float s_w1[64 * 64];
    __shared__ float s_w2[64 * 32];
    __shared__ float s_w3[32];
    __shared__ float s_b1[64];
    __shared__ float s_b2[32];
    __shared__ float s_b3;
    int t = threadIdx.x;
    for (int i = t; i < 64 * 16; i += 128) ((float4*)s_w1)[i] = ((const float4*)lw1)[i];
    for (int i = t; i < 64 * 8;  i += 128) ((float4*)s_w2)[i] = ((const float4*)lw2)[i];
    if (t < 32) s_w3[t] = lw3[t];
    if (t < 64) s_b1[t] = lb1[t];
    if (t < 32) s_b2[t] = lb2[t];
    if (t == 0) s_b3 = lb3[0];
    __syncthreads();

    int v = blockIdx.x * 128 + t;
    if (v >= NN) return;

    float in[64];
    const uint4* hr = (const uint4*)(h + (size_t)v * 32);
    #pragma unroll
    for (int i = 0; i < 8; i++) {
        uint4 q = hr[i];
        float2 f0 = __half22float2(*(__half2*)&q.x);
        float2 f1 = __half22float2(*(__half2*)&q.y);
        float2 f2 = __half22float2(*(__half2*)&q.z);
        float2 f3 = __half22float2(*(__half2*)&q.w);
        in[8 * i + 0] = f0.x; in[8 * i + 1] = f0.y;
        in[8 * i + 2] = f1.x; in[8 * i + 3] = f1.y;
        in[8 * i + 4] = f2.x; in[8 * i + 5] = f2.y;
        in[8 * i + 6] = f3.x; in[8 * i + 7] = f3.y;
    }

    // layer1: 64 -> 64
    ull a1[32];
    #pragma unroll
    for (int j = 0; j < 32; j++) a1[j] = ((const ull*)s_b1)[j];
    #pragma unroll
    for (int k = 0; k < 64; k++) {
        ull xs2 = bcast2(in[k]);
        const ull* wr = (const ull*)&s_w1[k * 64];
        #pragma unroll
        for (int j = 0; j < 32; j++) ffma2(a1[j], xs2, wr[j]);
    }
    float t1[64];
    #pragma unroll
    for (int j = 0; j < 32; j++) {
        float2 f = *(float2*)&a1[j];
        t1[2 * j]     = fmaxf(f.x, 0.f);
        t1[2 * j + 1] = fmaxf(f.y, 0.f);
    }

    // layer2: 64 -> 32
    ull a2[16];
    #pragma unroll
    for (int j = 0; j < 16; j++) a2[j] = ((const ull*)s_b2)[j];
    #pragma unroll
    for (int k = 0; k < 64; k++) {
        ull xs2 = bcast2(t1[k]);
        const ull* wr = (const ull*)&s_w2[k * 32];
        #pragma unroll
        for (int j = 0; j < 16; j++) ffma2(a2[j], xs2, wr[j]);
    }
    float t2[32];
    #pragma unroll
    for (int j = 0; j < 16; j++) {
        float2 f = *(float2*)&a2[j];
        t2[2 * j]     = fmaxf(f.x, 0.f);
        t2[2 * j + 1] = fmaxf(f.y, 0.f);
    }

    // layer3: 32 -> 1
    float o = s_b3;
    #pragma unroll
    for (int k = 0; k < 32; k++) o += t2[k] * s_w3[k];
    out[v] = o;
}

// ---------------- launcher (two-stream fork/join, capture-safe) ----------------
extern "C" void kernel_launch(void* const* d_in, const int* in_sizes, int n_in,
                              void* d_out, int out_size) {
    const float* x   = (const float*)d_in[0];
    const void*  edg = d_in[1];
    const float* W1  = (const float*)d_in[2];
    const float* b1  = (const float*)d_in[3];
    const float* W2  = (const float*)d_in[4];
    const float* b2  = (const float*)d_in[5];
    const float* lw1 = (const float*)d_in[6];
    const float* lb1 = (const float*)d_in[7];
    const float* lw2 = (const float*)d_in[8];
    const float* lb2 = (const float*)d_in[9];
    const float* lw3 = (const float*)d_in[10];
    const float* lb3 = (const float*)d_in[11];
    float* out = (float*)d_out;

    __half2* hh; cudaGetSymbolAddress((void**)&hh, g_hh);
    __half2* hf; cudaGetSymbolAddress((void**)&hf, g_hf);

    // one-time host-side resources (created on the uncaptured correctness call)
    static cudaStream_t s1 = nullptr;
    static cudaEvent_t evStart = nullptr, evG = nullptr;
    if (s1 == nullptr) {
        cudaStreamCreateWithFlags(&s1, cudaStreamNonBlocking);
        cudaEventCreateWithFlags(&evStart, cudaEventDisableTiming);
        cudaEventCreateWithFlags(&evG,     cudaEventDisableTiming);
    }

    // fork: s1 runs gemm128 (input-only deps) under the bucket fill
    cudaEventRecord(evStart, 0);
    cudaStreamWaitEvent(s1, evStart, 0);
    k_gemm128<<<GB, 256, 0, s1>>>(x, W1, hh);
    cudaEventRecord(evG, s1);

    // main stream: single-pass bucket CSR build (cursor pre-zeroed)
    k_fillb<<<E2B, 256>>>(edg);

    // join gemm, then dinv/deg + scale + cursor re-arm
    cudaStreamWaitEvent(0, evG, 0);
    k_scale2<<<(NN * 8 + 255) / 256, 256>>>((uint4*)hh);

    // serial conv/MLP chain
    k_agg<<<(NN + 7) / 8, 256>>>((const uint4*)hh, b1, hf);
    k_gemm64h<<<GB, 256>>>(hf, W2, hh);
    k_agg<<<(NN + 7) / 8, 256>>>((const uint4*)hh, b2, hf);
    k_mlp<<<(NN + 127) / 128, 128>>>(hf, lw1, lb1, lw2, lb2, lw3, lb3, out);
}